// round 12
// baseline (speedup 1.0000x reference)
#include <cuda_runtime.h>
#include <math.h>
#include <stdint.h>

#define B_   2
#define T_   2048
#define C_   2048
#define H_   16
#define KVH_ 4
#define HD_  128
#define MROWS (B_*T_)   // 4096
#define KU   1024       // packed u32 columns (K=2048 bf16-pairs)

// ---------------- scratch (device globals; no allocations) ----------------
__device__ float g_Q[B_*T_*H_*HD_];
__device__ float g_K[B_*T_*KVH_*HD_];
__device__ float g_V[B_*T_*KVH_*HD_];       // tf32-rounded (for flash)
__device__ float g_Kt[B_*KVH_*HD_*T_];      // tf32-rounded, [d][s]
// split-bf16 packed operands: u32 = (bf16 k+1 | bf16 k)
__device__ uint32_t g_Xh[MROWS*KU];
__device__ uint32_t g_Xl[MROWS*KU];
__device__ uint32_t g_Oh[MROWS*KU];         // attention output, packed by flash
__device__ uint32_t g_Ol[MROWS*KU];
__device__ uint32_t g_Wqh[KU*(H_*HD_)];
__device__ uint32_t g_Wql[KU*(H_*HD_)];
__device__ uint32_t g_Wkh[KU*(KVH_*HD_)];
__device__ uint32_t g_Wkl[KU*(KVH_*HD_)];
__device__ uint32_t g_Wvh[KU*(KVH_*HD_)];
__device__ uint32_t g_Wvl[KU*(KVH_*HD_)];
__device__ uint32_t g_Woh[KU*C_];
__device__ uint32_t g_Wol[KU*C_];

// ==================== helpers ====================
__device__ __forceinline__ uint32_t smem_u32(const void* p) {
    uint32_t a;
    asm("{ .reg .u64 t; cvta.to.shared.u64 t, %1; cvt.u32.u64 %0, t; }"
        : "=r"(a) : "l"(p));
    return a;
}

__device__ __forceinline__ uint32_t f2tf(float f) {
    uint32_t r;
    asm("cvt.rna.tf32.f32 %0, %1;" : "=r"(r) : "f"(f));
    return r;
}

// pack two floats into bf16x2 (x0 -> low, x1 -> high)
__device__ __forceinline__ uint32_t pack_bf2(float x0, float x1) {
    uint32_t r;
    asm("cvt.rn.bf16x2.f32 %0, %1, %2;" : "=r"(r) : "f"(x1), "f"(x0));
    return r;
}
// split a float pair into hi/lo bf16x2 packs
__device__ __forceinline__ void split_bf2(float x0, float x1,
                                          uint32_t& hp, uint32_t& lp) {
    hp = pack_bf2(x0, x1);
    float h0 = __uint_as_float(hp << 16);
    float h1 = __uint_as_float(hp & 0xFFFF0000u);
    lp = pack_bf2(x0 - h0, x1 - h1);
}

__device__ __forceinline__ void mma_tf32(float* c, const uint32_t* a, const uint32_t* b) {
    asm volatile(
        "mma.sync.aligned.m16n8k8.row.col.f32.tf32.tf32.f32 "
        "{%0,%1,%2,%3}, {%4,%5,%6,%7}, {%8,%9}, {%0,%1,%2,%3};"
        : "+f"(c[0]), "+f"(c[1]), "+f"(c[2]), "+f"(c[3])
        : "r"(a[0]), "r"(a[1]), "r"(a[2]), "r"(a[3]), "r"(b[0]), "r"(b[1]));
}

__device__ __forceinline__ void mma_bf16(float* c, const uint32_t* a, const uint32_t* b) {
    asm volatile(
        "mma.sync.aligned.m16n8k16.row.col.f32.bf16.bf16.f32 "
        "{%0,%1,%2,%3}, {%4,%5,%6,%7}, {%8,%9}, {%0,%1,%2,%3};"
        : "+f"(c[0]), "+f"(c[1]), "+f"(c[2]), "+f"(c[3])
        : "r"(a[0]), "r"(a[1]), "r"(a[2]), "r"(a[3]), "r"(b[0]), "r"(b[1]));
}

#define CPA16(dst, src) \
    asm volatile("cp.async.cg.shared.global [%0], [%1], 16;" \
                 :: "r"(dst), "l"(src) : "memory")
#define CP_COMMIT() asm volatile("cp.async.commit_group;" ::: "memory")
#define CP_WAIT1()  asm volatile("cp.async.wait_group 1;" ::: "memory")
#define CP_WAIT0()  asm volatile("cp.async.wait_group 0;" ::: "memory")

// =====================================================================
// Packing kernels (one-time): fp32 -> split-bf16 packed u32
// =====================================================================
// row-major A: src [M][K] -> hi/lo [M][K/2]
__global__ void __launch_bounds__(256) pack_row(
    const float* __restrict__ src, uint32_t* __restrict__ hi,
    uint32_t* __restrict__ lo, int n)
{
    int i = blockIdx.x * 256 + threadIdx.x;
    if (i < n) {
        float2 v = *(const float2*)(src + (long)i * 2);
        uint32_t hp, lp;
        split_bf2(v.x, v.y, hp, lp);
        hi[i] = hp; lo[i] = lp;
    }
}
// k-major W: src [K][N] -> hi/lo [K/2][N], pairing adjacent k rows
__global__ void __launch_bounds__(256) pack_kmaj(
    const float* __restrict__ W, uint32_t* __restrict__ hi,
    uint32_t* __restrict__ lo, int N, int n)
{
    int i = blockIdx.x * 256 + threadIdx.x;
    if (i < n) {
        int kk = i / N, c = i - kk * N;
        float x0 = W[(long)(2*kk)   * N + c];
        float x1 = W[(long)(2*kk+1) * N + c];
        uint32_t hp, lp;
        split_bf2(x0, x1, hp, lp);
        hi[i] = hp; lo[i] = lp;
    }
}

// =====================================================================
// split-bf16 GEMM core: CTA tile 256x128, 8 warps (4m x 2n), warp 64x64.
// Per k16 slice: 3x mma.m16n8k16.bf16 (Ah*Bh + Ah*Bl + Al*Bh).
// 3-stage cp.async pipeline, stage = 16 u32 cols (k32 floats).
// =====================================================================
#define ASTR 20
#define BSTR 132
#define A_ST (256*ASTR)        // 5120 u32 per stage per half
#define B_ST (16*BSTR)         // 2112 u32 per stage per half
#define GEMM_SMEM (3*(2*A_ST + 2*B_ST)*4)   // 173568 B

__device__ __forceinline__ void gemm_core(
    const uint32_t* __restrict__ Ah, const uint32_t* __restrict__ Al,
    const uint32_t* __restrict__ Wh, const uint32_t* __restrict__ Wl,
    const float* __restrict__ bias, float* __restrict__ Cout,
    int N, int rnd, int rowBlk, int colBlk)
{
    extern __shared__ uint32_t dsm[];
    uint32_t* AsH = dsm;                   // [3][A_ST]
    uint32_t* AsL = dsm + 3*A_ST;
    uint32_t* BsH = dsm + 6*A_ST;          // [3][B_ST]
    uint32_t* BsL = dsm + 6*A_ST + 3*B_ST;
    const uint32_t sbAH = smem_u32(AsH);
    const uint32_t sbAL = smem_u32(AsL);
    const uint32_t sbBH = smem_u32(BsH);
    const uint32_t sbBL = smem_u32(BsL);

    const int tid  = threadIdx.x;
    const int wid  = tid >> 5;
    const int lane = tid & 31;
    const int g    = lane >> 2;
    const int tg   = lane & 3;
    const int warp_m = (wid & 3) * 64;
    const int warp_n = (wid >> 2) * 64;

    float acc[4][8][4];
#pragma unroll
    for (int mt = 0; mt < 4; mt++)
#pragma unroll
        for (int nt = 0; nt < 8; nt++)
#pragma unroll
            for (int i = 0; i < 4; i++) acc[mt][nt][i] = 0.f;

    const int nit = KU / 16;   // 64 stages of 16 u32 cols

    auto prefetch = [&](int t, int s) {
#pragma unroll
        for (int i = 0; i < 4; i++) {
            int idx = tid + i * 256;
            int r = idx >> 2, c = (idx & 3) * 4;
            long goff = (long)(rowBlk + r) * KU + t*16 + c;
            uint32_t soff = (uint32_t)(s*A_ST + r*ASTR + c) * 4u;
            CPA16(sbAH + soff, (const void*)(Ah + goff));
            CPA16(sbAL + soff, (const void*)(Al + goff));
        }
#pragma unroll
        for (int i = 0; i < 2; i++) {
            int idx = tid + i * 256;
            int k = idx >> 5, n4 = (idx & 31) * 4;
            long goff = (long)(t*16 + k) * N + colBlk + n4;
            uint32_t soff = (uint32_t)(s*B_ST + k*BSTR + n4) * 4u;
            CPA16(sbBH + soff, (const void*)(Wh + goff));
            CPA16(sbBL + soff, (const void*)(Wl + goff));
        }
        CP_COMMIT();
    };

    prefetch(0, 0);
    prefetch(1, 1);

    for (int it = 0; it < nit; it++) {
        const int cur = it % 3;
        if (it == nit - 1) { CP_WAIT0(); } else { CP_WAIT1(); }
        __syncthreads();
        if (it + 2 < nit) prefetch(it + 2, (it + 2) % 3);

        const uint32_t* AH = AsH + cur * A_ST;
        const uint32_t* AL = AsL + cur * A_ST;
        const uint32_t* BH = BsH + cur * B_ST;
        const uint32_t* BL = BsL + cur * B_ST;

#pragma unroll
        for (int s = 0; s < 2; s++) {      // two k16 slices per stage
            uint32_t ah[4][4], al[4][4];
#pragma unroll
            for (int mt = 0; mt < 4; mt++) {
                int row = warp_m + mt * 16 + g;
                int c0  = s * 8 + tg;
                ah[mt][0] = AH[row * ASTR + c0];
                ah[mt][1] = AH[(row + 8) * ASTR + c0];
                ah[mt][2] = AH[row * ASTR + c0 + 4];
                ah[mt][3] = AH[(row + 8) * ASTR + c0 + 4];
                al[mt][0] = AL[row * ASTR + c0];
                al[mt][1] = AL[(row + 8) * ASTR + c0];
                al[mt][2] = AL[row * ASTR + c0 + 4];
                al[mt][3] = AL[(row + 8) * ASTR + c0 + 4];
            }
#pragma unroll
            for (int nt = 0; nt < 8; nt++) {
                int col = warp_n + nt * 8 + g;
                uint32_t bh[2], bl[2];
                bh[0] = BH[(s*8 + tg)     * BSTR + col];
                bh[1] = BH[(s*8 + tg + 4) * BSTR + col];
                bl[0] = BL[(s*8 + tg)     * BSTR + col];
                bl[1] = BL[(s*8 + tg + 4) * BSTR + col];
#pragma unroll
                for (int mt = 0; mt < 4; mt++) {
                    mma_bf16(acc[mt][nt], ah[mt], bl);
                    mma_bf16(acc[mt][nt], al[mt], bh);
                    mma_bf16(acc[mt][nt], ah[mt], bh);
                }
            }
        }
    }

#pragma unroll
    for (int mt = 0; mt < 4; mt++) {
        int row = rowBlk + warp_m + mt * 16 + g;
#pragma unroll
        for (int nt = 0; nt < 8; nt++) {
            int col = colBlk + warp_n + nt * 8 + 2 * tg;
            float b0 = 0.f, b1 = 0.f;
            if (bias) { b0 = bias[col]; b1 = bias[col + 1]; }
            float v0 = acc[mt][nt][0] + b0, v1 = acc[mt][nt][1] + b1;
            float v2 = acc[mt][nt][2] + b0, v3 = acc[mt][nt][3] + b1;
            if (rnd) {   // tf32-round (V feeds flash cp.async truncation)
                v0 = __uint_as_float(f2tf(v0)); v1 = __uint_as_float(f2tf(v1));
                v2 = __uint_as_float(f2tf(v2)); v3 = __uint_as_float(f2tf(v3));
            }
            float* c0 = Cout + (long)row * N + col;
            float* c1 = Cout + (long)(row + 8) * N + col;
            *(float2*)c0 = make_float2(v0, v1);
            *(float2*)c1 = make_float2(v2, v3);
        }
    }
}

// Merged QKV projection: grid (24, 16). bx<16: Q, <20: K, else V.
__global__ void __launch_bounds__(256, 1) qkv_mma(
    const float* __restrict__ bq, float* __restrict__ qp,
    const float* __restrict__ bk, float* __restrict__ kp,
    const float* __restrict__ bv, float* __restrict__ vp)
{
    const int bx = blockIdx.x;
    const int rowBlk = blockIdx.y * 256;
    if (bx < 16)
        gemm_core(g_Xh, g_Xl, g_Wqh, g_Wql, bq, qp, H_*HD_,   0, rowBlk, bx * 128);
    else if (bx < 20)
        gemm_core(g_Xh, g_Xl, g_Wkh, g_Wkl, bk, kp, KVH_*HD_, 0, rowBlk, (bx - 16) * 128);
    else
        gemm_core(g_Xh, g_Xl, g_Wvh, g_Wvl, bv, vp, KVH_*HD_, 1, rowBlk, (bx - 20) * 128);
}

// Output projection: grid (16, 16)
__global__ void __launch_bounds__(256, 1) out_mma(float* __restrict__ out)
{
    gemm_core(g_Oh, g_Ol, g_Woh, g_Wol, nullptr, out, C_, 0,
              blockIdx.y * 256, blockIdx.x * 128);
}

// =====================================================================
// RoPE on Q, in place.
// =====================================================================
__global__ void __launch_bounds__(256) rope_q_kernel()
{
    int idx = blockIdx.x * 256 + threadIdx.x;
    int d  = idx & 63;
    int rh = idx >> 6;
    int h  = rh & (H_ - 1);
    int bt = rh >> 4;
    int t  = bt & (T_ - 1);
    long base = (long)bt * (H_*HD_) + h * HD_;
    float invf = expf(-(float)d * (9.210340371976184f / 64.0f));
    float sn, cs;
    sincosf((float)t * invf, &sn, &cs);
    float x1 = g_Q[base + d];
    float x2 = g_Q[base + d + 64];
    g_Q[base + d]      = x1 * cs - x2 * sn;
    g_Q[base + d + 64] = x2 * cs + x1 * sn;
}

// =====================================================================
// RoPE on K + transpose to [B,KVH,HD,T]; output tf32-ROUNDED.
// =====================================================================
__global__ void __launch_bounds__(256) ropeT_k_kernel()
{
    __shared__ float sm1[32][33];
    __shared__ float sm2[32][33];
    const int tid = threadIdx.x;
    const int s0  = blockIdx.x * 32;
    const int d0  = blockIdx.y * 32;
    const int bkh = blockIdx.z;
    const int b   = bkh >> 2;
    const int kh  = bkh & 3;

    {
        int r  = tid >> 3;
        int c4 = (tid & 7) * 4;
        long gbase = (long)(b*T_ + s0 + r) * (KVH_*HD_) + kh * HD_;
        float4 v1 = *(const float4*)(g_K + gbase + d0 + c4);
        float4 v2 = *(const float4*)(g_K + gbase + d0 + 64 + c4);
        sm1[r][c4+0]=v1.x; sm1[r][c4+1]=v1.y; sm1[r][c4+2]=v1.z; sm1[r][c4+3]=v1.w;
        sm2[r][c4+0]=v2.x; sm2[r][c4+1]=v2.y; sm2[r][c4+2]=v2.z; sm2[r][c4+3]=v2.w;
    }
    __syncthreads();

    const int dl = tid >> 2;
    const int cg = tid & 3;
    const int dd = dl & 31;
    float invf = expf(-(float)(d0 + dd) * (9.210340371976184f / 64.0f));
    int dglob = (dl < 32) ? (d0 + dd) : (64 + d0 + dd);
    long obase = (long)(bkh * HD_ + dglob) * T_;
#pragma unroll
    for (int i = 0; i < 8; i++) {
        int cc = cg * 8 + i;
        int t  = s0 + cc;
        float sn, cs;
        sincosf((float)t * invf, &sn, &cs);
        float x1 = sm1[cc][dd];
        float x2 = sm2[cc][dd];
        float out = (dl < 32) ? (x1 * cs - x2 * sn) : (x2 * cs + x1 * sn);
        g_Kt[obase + t] = __uint_as_float(f2tf(out));
    }
}

// =====================================================================
// Tensor-core flash attention (causal, GQA). tf32 (proven structure).
// CTA order reversed (big causal tiles first). Epilogue writes
// split-bf16-packed O directly (feeds the bf16 out-projection).
// =====================================================================
#define FQS 132
#define FKS 68
#define FVS 132
#define KOFF 67584
#define KSZ  34816
#define VOFF (KOFF + 2*KSZ)
#define VSZ  33792
#define FLASH_SMEM (VOFF + 2*VSZ)  // 204800

__global__ void __launch_bounds__(256) flash_tc()
{
    extern __shared__ char smem[];
    uint32_t* Qs  = (uint32_t*)smem;
    const uint32_t sb = smem_u32(smem);

    const int tid = threadIdx.x;
    const int qt  = gridDim.x - 1 - blockIdx.x;   // big tiles first
    const int h   = blockIdx.y;
    const int b   = blockIdx.z;
    const int kh  = h >> 2;
    const int t0  = qt * 128;
    const int wm  = (tid >> 5) * 16;
    const int lane = tid & 31;
    const int g = lane >> 2, tg = lane & 3;

    const float* kg = g_Kt + (long)(b*KVH_ + kh) * HD_ * T_;
    const float* vg = g_V  + (long)b*T_*(KVH_*HD_) + kh*HD_;
    const float scale = 0.08838834764831845f;

    {
        const float* qg = g_Q + (long)(b*T_ + t0) * (H_*HD_) + h*HD_;
#pragma unroll
        for (int it = 0; it < 16; it++) {
            int idx = tid + it*256;
            int r = idx >> 5, d4 = (idx & 31) * 4;
            float4 v = *(const float4*)(qg + (long)r*(H_*HD_) + d4);
            uint32_t* qp = &Qs[r*FQS + d4];
            qp[0] = f2tf(v.x * scale); qp[1] = f2tf(v.y * scale);
            qp[2] = f2tf(v.z * scale); qp[3] = f2tf(v.w * scale);
        }
    }

    const int nkt = 2*qt + 2;

    {
        const int s0n = 0;
#pragma unroll
        for (int it = 0; it < 8; it++) {
            int idx = tid + it*256;
            int d = idx >> 4, c4 = (idx & 15) * 4;
            CPA16(sb + KOFF + (d*FKS + c4)*4, (const void*)(kg + (long)d*T_ + s0n + c4));
        }
#pragma unroll
        for (int it = 0; it < 8; it++) {
            int idx = tid + it*256;
            int c = idx >> 5, d4 = (idx & 31) * 4;
            CPA16(sb + VOFF + (c*FVS + d4)*4, (const void*)(vg + (long)(s0n + c)*(KVH_*HD_) + d4));
        }
        CP_COMMIT();
    }

    float o[16][4];
#pragma unroll
    for (int nt = 0; nt < 16; nt++)
#pragma unroll
        for (int i = 0; i < 4; i++) o[nt][i] = 0.f;
    float m0 = -1e30f, m1 = -1e30f, l0 = 0.f, l1 = 0.f;

    for (int kt = 0; kt < nkt; kt++) {
        const int cur = kt & 1;
        if (kt + 1 < nkt) {
            const int s0n = (kt + 1) * 64;
            const int sel = cur ^ 1;
#pragma unroll
            for (int it = 0; it < 8; it++) {
                int idx = tid + it*256;
                int d = idx >> 4, c4 = (idx & 15) * 4;
                CPA16(sb + KOFF + sel*KSZ + (d*FKS + c4)*4,
                      (const void*)(kg + (long)d*T_ + s0n + c4));
            }
#pragma unroll
            for (int it = 0; it < 8; it++) {
                int idx = tid + it*256;
                int c = idx >> 5, d4 = (idx & 31) * 4;
                CPA16(sb + VOFF + sel*VSZ + (c*FVS + d4)*4,
                      (const void*)(vg + (long)(s0n + c)*(KVH_*HD_) + d4));
            }
            CP_COMMIT();
            CP_WAIT1();
        } else {
            CP_WAIT0();
        }
        __syncthreads();

        const uint32_t* Kc = (const uint32_t*)(smem + KOFF + cur*KSZ);
        const uint32_t* Vc = (const uint32_t*)(smem + VOFF + cur*VSZ);

        float sf[8][4];
#pragma unroll
        for (int nt = 0; nt < 8; nt++)
#pragma unroll
            for (int i = 0; i < 4; i++) sf[nt][i] = 0.f;

#pragma unroll
        for (int kd = 0; kd < 16; kd++) {
            uint32_t a[4];
            a[0] = Qs[(wm+g)*FQS   + kd*8 + tg];
            a[1] = Qs[(wm+g+8)*FQS + kd*8 + tg];
            a[2] = Qs[(wm+g)*FQS   + kd*8 + tg + 4];
            a[3] = Qs[(wm+g+8)*FQS + kd*8 + tg + 4];
#pragma unroll
            for (int nt = 0; nt < 8; nt++) {
                uint32_t bb[2];
                bb[0] = Kc[(kd*8+tg)*FKS   + nt*8 + g];
                bb[1] = Kc[(kd*8+tg+4)*FKS + nt*8 + g];
                mma_tf32(sf[nt], a, bb);
            }
        }

        if (kt >= nkt - 2) {
            const int s0c = kt * 64;
            const int r0 = t0 + wm + g, r1 = r0 + 8;
#pragma unroll
            for (int nt = 0; nt < 8; nt++) {
                int c0 = s0c + nt*8 + 2*tg;
                if (c0     > r0) sf[nt][0] = -1e30f;
                if (c0 + 1 > r0) sf[nt][1] = -1e30f;
                if (c0     > r1) sf[nt][2] = -1e30f;
                if (c0 + 1 > r1) sf[nt][3] = -1e30f;
            }
        }

        float mt0 = -1e30f, mt1 = -1e30f;
#pragma unroll
        for (int nt = 0; nt < 8; nt++) {
            mt0 = fmaxf(mt0, fmaxf(sf[nt][0], sf[nt][1]));
            mt1 = fmaxf(mt1, fmaxf(sf[nt][2], sf[nt][3]));
        }
        mt0 = fmaxf(mt0, __shfl_xor_sync(0xffffffffu, mt0, 1));
        mt0 = fmaxf(mt0, __shfl_xor_sync(0xffffffffu, mt0, 2));
        mt1 = fmaxf(mt1, __shfl_xor_sync(0xffffffffu, mt1, 1));
        mt1 = fmaxf(mt1, __shfl_xor_sync(0xffffffffu, mt1, 2));

        float mn0 = fmaxf(m0, mt0), mn1 = fmaxf(m1, mt1);
        float al0 = __expf(m0 - mn0), al1 = __expf(m1 - mn1);
        m0 = mn0; m1 = mn1;

        float rs0 = 0.f, rs1 = 0.f;
        uint32_t pf[8][4];
#pragma unroll
        for (int nt = 0; nt < 8; nt++) {
            float p0 = __expf(sf[nt][0] - mn0);
            float p1 = __expf(sf[nt][1] - mn0);
            float p2 = __expf(sf[nt][2] - mn1);
            float p3 = __expf(sf[nt][3] - mn1);
            rs0 += p0 + p1; rs1 += p2 + p3;
            pf[nt][0] = f2tf(p0); pf[nt][1] = f2tf(p1);
            pf[nt][2] = f2tf(p2); pf[nt][3] = f2tf(p3);
        }
        rs0 += __shfl_xor_sync(0xffffffffu, rs0, 1);
        rs0 += __shfl_xor_sync(0xffffffffu, rs0, 2);
        rs1 += __shfl_xor_sync(0xffffffffu, rs1, 1);
        rs1 += __shfl_xor_sync(0xffffffffu, rs1, 2);
        l0 = l0 * al0 + rs0;
        l1 = l1 * al1 + rs1;

#pragma unroll
        for (int nt = 0; nt < 16; nt++) {
            o[nt][0] *= al0; o[nt][1] *= al0;
            o[nt][2] *= al1; o[nt][3] *= al1;
        }

#pragma unroll
        for (int ks = 0; ks < 8; ks++) {
            const int src1 = (g << 2) | (tg >> 1);
            uint32_t u0 = __shfl_sync(0xffffffffu, pf[ks][0], src1);
            uint32_t u1 = __shfl_sync(0xffffffffu, pf[ks][1], src1);
            uint32_t u2 = __shfl_sync(0xffffffffu, pf[ks][2], src1);
            uint32_t u3 = __shfl_sync(0xffffffffu, pf[ks][3], src1);
            uint32_t w0 = __shfl_sync(0xffffffffu, pf[ks][0], src1 + 2);
            uint32_t w1 = __shfl_sync(0xffffffffu, pf[ks][1], src1 + 2);
            uint32_t w2 = __shfl_sync(0xffffffffu, pf[ks][2], src1 + 2);
            uint32_t w3 = __shfl_sync(0xffffffffu, pf[ks][3], src1 + 2);
            uint32_t a[4];
            a[0] = (tg & 1) ? u1 : u0;
            a[1] = (tg & 1) ? u3 : u2;
            a[2] = (tg & 1) ? w1 : w0;
            a[3] = (tg & 1) ? w3 : w2;
#pragma unroll
            for (int nt = 0; nt < 16; nt++) {
                uint32_t bb[2];
                bb[0] = Vc[(ks*8+tg)*FVS   + nt*8 + g];
                bb[1] = Vc[(ks*8+tg+4)*FVS + nt*8 + g];
                mma_tf32(o[nt], a, bb);
            }
        }
        __syncthreads();
    }

    // ---- epilogue: normalize + split-bf16 pack into g_Oh/g_Ol ----
    const float inv0 = 1.0f / l0, inv1 = 1.0f / l1;
    const long row0 = (long)(b*T_ + t0 + wm + g);
    const long row1 = row0 + 8;
    const int colbase = h * 64;   // packed col offset for this head
#pragma unroll
    for (int nt = 0; nt < 16; nt++) {
        int p = colbase + nt*4 + tg;
        uint32_t hp, lp;
        split_bf2(o[nt][0]*inv0, o[nt][1]*inv0, hp, lp);
        g_Oh[row0*KU + p] = hp; g_Ol[row0*KU + p] = lp;
        split_bf2(o[nt][2]*inv1, o[nt][3]*inv1, hp, lp);
        g_Oh[row1*KU + p] = hp; g_Ol[row1*KU + p] = lp;
    }
}

// =====================================================================
// host launcher
// =====================================================================
extern "C" void kernel_launch(void* const* d_in, const int* in_sizes, int n_in,
                              void* d_out, int out_size)
{
    const float* x  = (const float*)d_in[0];
    const float* wq = (const float*)d_in[1];
    const float* bq = (const float*)d_in[2];
    const float* wk = (const float*)d_in[3];
    const float* bk = (const float*)d_in[4];
    const float* wv = (const float*)d_in[5];
    const float* bv = (const float*)d_in[6];
    const float* wo = (const float*)d_in[7];
    float* out = (float*)d_out;

    float *qp, *kp, *vp;
    uint32_t *xh, *xl, *wqh, *wql, *wkh, *wkl, *wvh, *wvl, *woh, *wol;
    cudaGetSymbolAddress((void**)&qp, g_Q);
    cudaGetSymbolAddress((void**)&kp, g_K);
    cudaGetSymbolAddress((void**)&vp, g_V);
    cudaGetSymbolAddress((void**)&xh,  g_Xh);
    cudaGetSymbolAddress((void**)&xl,  g_Xl);
    cudaGetSymbolAddress((void**)&wqh, g_Wqh);
    cudaGetSymbolAddress((void**)&wql, g_Wql);
    cudaGetSymbolAddress((void**)&wkh, g_Wkh);
    cudaGetSymbolAddress((void**)&wkl, g_Wkl);
    cudaGetSymbolAddress((void**)&wvh, g_Wvh);
    cudaGetSymbolAddress((void**)&wvl, g_Wvl);
    cudaGetSymbolAddress((void**)&woh, g_Woh);
    cudaGetSymbolAddress((void**)&wol, g_Wol);

    cudaFuncSetAttribute(flash_tc,
                         cudaFuncAttributeMaxDynamicSharedMemorySize, FLASH_SMEM);
    cudaFuncSetAttribute(qkv_mma,
                         cudaFuncAttributeMaxDynamicSharedMemorySize, GEMM_SMEM);
    cudaFuncSetAttribute(out_mma,
                         cudaFuncAttributeMaxDynamicSharedMemorySize, GEMM_SMEM);

    dim3 blk(256);

    // split-bf16 packing of GEMM operands
    pack_row <<<(MROWS*KU)/256, blk>>>(x, xh, xl, MROWS*KU);
    pack_kmaj<<<(KU*(H_*HD_))/256,   blk>>>(wq, wqh, wql, H_*HD_,   KU*(H_*HD_));
    pack_kmaj<<<(KU*(KVH_*HD_))/256, blk>>>(wk, wkh, wkl, KVH_*HD_, KU*(KVH_*HD_));
    pack_kmaj<<<(KU*(KVH_*HD_))/256, blk>>>(wv, wvh, wvl, KVH_*HD_, KU*(KVH_*HD_));
    pack_kmaj<<<(KU*C_)/256,         blk>>>(wo, woh, wol, C_,       KU*C_);

    // merged QKV projection (split-bf16 tensor cores)
    qkv_mma<<<dim3(24, MROWS/256), blk, GEMM_SMEM>>>(bq, qp, bk, kp, bv, vp);

    // RoPE
    rope_q_kernel<<<(B_*T_*H_*64)/256, blk>>>();
    ropeT_k_kernel<<<dim3(T_/32, 2, B_*KVH_), blk>>>();

    // flash attention (tf32; writes packed O)
    flash_tc<<<dim3(T_/128, H_, B_), blk, FLASH_SMEM>>>();

    // output projection (split-bf16)
    out_mma<<<dim3(C_/128, MROWS/256), blk, GEMM_SMEM>>>(out);
}

// round 14
// speedup vs baseline: 2.0206x; 2.0206x over previous
#include <cuda_runtime.h>
#include <math.h>
#include <stdint.h>

#define B_   2
#define T_   2048
#define C_   2048
#define H_   16
#define KVH_ 4
#define HD_  128
#define MROWS (B_*T_)   // 4096
#define KU   1024       // packed u32 columns (2048 fp16 pairs)

// ---------------- scratch (device globals; no allocations) ----------------
__device__ float g_Q[B_*T_*H_*HD_];          // fp32 (RoPE in place)
__device__ float g_K[B_*T_*KVH_*HD_];        // fp32
__device__ float g_V[B_*T_*KVH_*HD_];        // fp32
__device__ float g_Kt[B_*KVH_*HD_*T_];       // fp32, [d][s] per (b,kh)
// fp16-packed operands (u32 = hi<<16 | lo, lo = even index)
__device__ uint32_t g_Xp[MROWS*KU];          // x packed along k
__device__ uint32_t g_Op[MROWS*KU];          // attention out, packed by flash
__device__ uint32_t g_Wqp[KU*(H_*HD_)];
__device__ uint32_t g_Wkp[KU*(KVH_*HD_)];
__device__ uint32_t g_Wvp[KU*(KVH_*HD_)];
__device__ uint32_t g_Wop[KU*C_];
__device__ uint32_t g_Ktp[B_*KVH_*64*T_];    // K^T packed along d: [bkh][dpair][s]
__device__ uint32_t g_Vp[B_*KVH_*(T_/2)*HD_];// V packed along s: [bkh][spair][d]

// ==================== helpers ====================
__device__ __forceinline__ uint32_t smem_u32(const void* p) {
    uint32_t a;
    asm("{ .reg .u64 t; cvta.to.shared.u64 t, %1; cvt.u32.u64 %0, t; }"
        : "=r"(a) : "l"(p));
    return a;
}

// pack two floats into fp16x2 (x0 -> low half, x1 -> high half)
__device__ __forceinline__ uint32_t pack_h2(float x0, float x1) {
    uint32_t r;
    asm("cvt.rn.f16x2.f32 %0, %1, %2;" : "=r"(r) : "f"(x1), "f"(x0));
    return r;
}

__device__ __forceinline__ void mma_fp16(float* c, const uint32_t* a, const uint32_t* b) {
    asm volatile(
        "mma.sync.aligned.m16n8k16.row.col.f32.f16.f16.f32 "
        "{%0,%1,%2,%3}, {%4,%5,%6,%7}, {%8,%9}, {%0,%1,%2,%3};"
        : "+f"(c[0]), "+f"(c[1]), "+f"(c[2]), "+f"(c[3])
        : "r"(a[0]), "r"(a[1]), "r"(a[2]), "r"(a[3]), "r"(b[0]), "r"(b[1]));
}

#define CPA16(dst, src) \
    asm volatile("cp.async.cg.shared.global [%0], [%1], 16;" \
                 :: "r"(dst), "l"(src) : "memory")
#define CP_COMMIT() asm volatile("cp.async.commit_group;" ::: "memory")
#define CP_WAIT1()  asm volatile("cp.async.wait_group 1;" ::: "memory")
#define CP_WAIT0()  asm volatile("cp.async.wait_group 0;" ::: "memory")

// =====================================================================
// Packing kernels
// =====================================================================
__global__ void __launch_bounds__(256) pack_row(
    const float* __restrict__ src, uint32_t* __restrict__ dst, int n)
{
    int i = blockIdx.x * 256 + threadIdx.x;
    if (i < n) {
        float2 v = *(const float2*)(src + (long)i * 2);
        dst[i] = pack_h2(v.x, v.y);
    }
}
__global__ void __launch_bounds__(256) pack_kmaj(
    const float* __restrict__ W, uint32_t* __restrict__ dst, int N, int n)
{
    int i = blockIdx.x * 256 + threadIdx.x;
    if (i < n) {
        int kk = i / N, c = i - kk * N;
        dst[i] = pack_h2(W[(long)(2*kk) * N + c], W[(long)(2*kk+1) * N + c]);
    }
}
// g_Kt [bkh*128 + d][T] -> g_Ktp [bkh*64 + dp][T] (pairs along d)
__global__ void __launch_bounds__(256) pack_kt()
{
    int i = blockIdx.x * 256 + threadIdx.x;   // over 512*T_
    int s   = i & (T_ - 1);
    int dpr = i >> 11;                        // bkh*64 + dp
    int bkh = dpr >> 6, dp = dpr & 63;
    long r0 = (long)(bkh*128 + 2*dp) * T_ + s;
    g_Ktp[(long)dpr * T_ + s] = pack_h2(g_Kt[r0], g_Kt[r0 + T_]);
}
// g_V [b*T+s][kh*128+d] -> g_Vp [bkh][sp][128] (pairs along s)
__global__ void __launch_bounds__(256) pack_v()
{
    int i = blockIdx.x * 256 + threadIdx.x;   // over 8*1024*128
    int d    = i & 127;
    int rest = i >> 7;
    int sp   = rest & 1023;
    int bkh  = rest >> 10;
    int b = bkh >> 2, kh = bkh & 3;
    long s0 = (long)(b*T_ + 2*sp) * (KVH_*HD_) + kh*HD_ + d;
    g_Vp[i] = pack_h2(g_V[s0], g_V[s0 + KVH_*HD_]);
}

// =====================================================================
// fp16 GEMM core: CTA 256x128, 8 warps (4m x 2n), warp 64x64.
// One m16n8k16 mma per k16 slice. 3-stage cp.async, one sync per stage.
// =====================================================================
#define ASTR 20
#define BSTR 132
#define A_ST (256*ASTR)
#define B_ST (16*BSTR)
#define GEMM_SMEM (3*(A_ST + B_ST)*4)

__device__ __forceinline__ void gemm_core(
    const uint32_t* __restrict__ Ap, const uint32_t* __restrict__ Wp,
    const float* __restrict__ bias, float* __restrict__ Cout,
    int N, int rowBlk, int colBlk)
{
    extern __shared__ uint32_t dsm[];
    uint32_t* As = dsm;                 // [3][A_ST]
    uint32_t* Bs = dsm + 3*A_ST;        // [3][B_ST]
    const uint32_t sbA = smem_u32(As);
    const uint32_t sbB = smem_u32(Bs);

    const int tid  = threadIdx.x;
    const int wid  = tid >> 5;
    const int lane = tid & 31;
    const int g    = lane >> 2;
    const int tg   = lane & 3;
    const int warp_m = (wid & 3) * 64;
    const int warp_n = (wid >> 2) * 64;

    float acc[4][8][4];
#pragma unroll
    for (int mt = 0; mt < 4; mt++)
#pragma unroll
        for (int nt = 0; nt < 8; nt++)
#pragma unroll
            for (int i = 0; i < 4; i++) acc[mt][nt][i] = 0.f;

    const int nit = KU / 16;   // 64 stages

    auto prefetch = [&](int t, int s) {
#pragma unroll
        for (int i = 0; i < 4; i++) {
            int idx = tid + i * 256;
            int r = idx >> 2, c = (idx & 3) * 4;
            CPA16(sbA + (uint32_t)(s*A_ST + r*ASTR + c) * 4u,
                  (const void*)(Ap + (long)(rowBlk + r) * KU + t*16 + c));
        }
#pragma unroll
        for (int i = 0; i < 2; i++) {
            int idx = tid + i * 256;
            int k = idx >> 5, n4 = (idx & 31) * 4;
            CPA16(sbB + (uint32_t)(s*B_ST + k*BSTR + n4) * 4u,
                  (const void*)(Wp + (long)(t*16 + k) * N + colBlk + n4));
        }
        CP_COMMIT();
    };

    prefetch(0, 0);
    prefetch(1, 1);

    for (int it = 0; it < nit; it++) {
        const int cur = it % 3;
        if (it == nit - 1) { CP_WAIT0(); } else { CP_WAIT1(); }
        __syncthreads();
        if (it + 2 < nit) prefetch(it + 2, (it + 2) % 3);

        const uint32_t* AS = As + cur * A_ST;
        const uint32_t* BS = Bs + cur * B_ST;

#pragma unroll
        for (int s = 0; s < 2; s++) {      // two k16 slices per stage
            uint32_t a[4][4];
#pragma unroll
            for (int mt = 0; mt < 4; mt++) {
                int row = warp_m + mt * 16 + g;
                int c0  = s * 8 + tg;
                a[mt][0] = AS[row * ASTR + c0];
                a[mt][1] = AS[(row + 8) * ASTR + c0];
                a[mt][2] = AS[row * ASTR + c0 + 4];
                a[mt][3] = AS[(row + 8) * ASTR + c0 + 4];
            }
#pragma unroll
            for (int nt = 0; nt < 8; nt++) {
                int col = warp_n + nt * 8 + g;
                uint32_t bb[2];
                bb[0] = BS[(s*8 + tg)     * BSTR + col];
                bb[1] = BS[(s*8 + tg + 4) * BSTR + col];
#pragma unroll
                for (int mt = 0; mt < 4; mt++)
                    mma_fp16(acc[mt][nt], a[mt], bb);
            }
        }
    }

#pragma unroll
    for (int mt = 0; mt < 4; mt++) {
        int row = rowBlk + warp_m + mt * 16 + g;
#pragma unroll
        for (int nt = 0; nt < 8; nt++) {
            int col = colBlk + warp_n + nt * 8 + 2 * tg;
            float b0 = 0.f, b1 = 0.f;
            if (bias) { b0 = bias[col]; b1 = bias[col + 1]; }
            float* c0 = Cout + (long)row * N + col;
            float* c1 = Cout + (long)(row + 8) * N + col;
            *(float2*)c0 = make_float2(acc[mt][nt][0] + b0, acc[mt][nt][1] + b1);
            *(float2*)c1 = make_float2(acc[mt][nt][2] + b0, acc[mt][nt][3] + b1);
        }
    }
}

// Merged QKV projection: grid (24, 16). bx<16: Q, <20: K, else V.
__global__ void __launch_bounds__(256, 1) qkv_mma(
    const float* __restrict__ bq, float* __restrict__ qp,
    const float* __restrict__ bk, float* __restrict__ kp,
    const float* __restrict__ bv, float* __restrict__ vp)
{
    const int bx = blockIdx.x;
    const int rowBlk = blockIdx.y * 256;
    if (bx < 16)
        gemm_core(g_Xp, g_Wqp, bq, qp, H_*HD_,   rowBlk, bx * 128);
    else if (bx < 20)
        gemm_core(g_Xp, g_Wkp, bk, kp, KVH_*HD_, rowBlk, (bx - 16) * 128);
    else
        gemm_core(g_Xp, g_Wvp, bv, vp, KVH_*HD_, rowBlk, (bx - 20) * 128);
}

// Output projection: grid (16, 16)
__global__ void __launch_bounds__(256, 1) out_mma(float* __restrict__ out)
{
    gemm_core(g_Op, g_Wop, nullptr, out, C_, blockIdx.y * 256, blockIdx.x * 128);
}

// =====================================================================
// RoPE on Q, in place (fp32).
// =====================================================================
__global__ void __launch_bounds__(256) rope_q_kernel()
{
    int idx = blockIdx.x * 256 + threadIdx.x;
    int d  = idx & 63;
    int rh = idx >> 6;
    int h  = rh & (H_ - 1);
    int bt = rh >> 4;
    int t  = bt & (T_ - 1);
    long base = (long)bt * (H_*HD_) + h * HD_;
    float invf = expf(-(float)d * (9.210340371976184f / 64.0f));
    float sn, cs;
    sincosf((float)t * invf, &sn, &cs);
    float x1 = g_Q[base + d];
    float x2 = g_Q[base + d + 64];
    g_Q[base + d]      = x1 * cs - x2 * sn;
    g_Q[base + d + 64] = x2 * cs + x1 * sn;
}

// =====================================================================
// RoPE on K + transpose to [B,KVH,HD,T] fp32 (pack_kt converts to fp16).
// =====================================================================
__global__ void __launch_bounds__(256) ropeT_k_kernel()
{
    __shared__ float sm1[32][33];
    __shared__ float sm2[32][33];
    const int tid = threadIdx.x;
    const int s0  = blockIdx.x * 32;
    const int d0  = blockIdx.y * 32;
    const int bkh = blockIdx.z;
    const int b   = bkh >> 2;
    const int kh  = bkh & 3;

    {
        int r  = tid >> 3;
        int c4 = (tid & 7) * 4;
        long gbase = (long)(b*T_ + s0 + r) * (KVH_*HD_) + kh * HD_;
        float4 v1 = *(const float4*)(g_K + gbase + d0 + c4);
        float4 v2 = *(const float4*)(g_K + gbase + d0 + 64 + c4);
        sm1[r][c4+0]=v1.x; sm1[r][c4+1]=v1.y; sm1[r][c4+2]=v1.z; sm1[r][c4+3]=v1.w;
        sm2[r][c4+0]=v2.x; sm2[r][c4+1]=v2.y; sm2[r][c4+2]=v2.z; sm2[r][c4+3]=v2.w;
    }
    __syncthreads();

    const int dl = tid >> 2;
    const int cg = tid & 3;
    const int dd = dl & 31;
    float invf = expf(-(float)(d0 + dd) * (9.210340371976184f / 64.0f));
    int dglob = (dl < 32) ? (d0 + dd) : (64 + d0 + dd);
    long obase = (long)(bkh * HD_ + dglob) * T_;
#pragma unroll
    for (int i = 0; i < 8; i++) {
        int cc = cg * 8 + i;
        int t  = s0 + cc;
        float sn, cs;
        sincosf((float)t * invf, &sn, &cs);
        float x1 = sm1[cc][dd];
        float x2 = sm2[cc][dd];
        float out = (dl < 32) ? (x1 * cs - x2 * sn) : (x2 * cs + x1 * sn);
        g_Kt[obase + t] = out;
    }
}

// =====================================================================
// fp16 tensor-core flash attention (causal, GQA).
// BM=128, BN=64, 256 threads (8 warps x 16 rows). m16n8k16 for S and PV.
// PV A-fragments come straight from the packed P registers (no shuffles).
// smem: Qs[128][68] | K[2][64][68] | V[2][32][132]  = 103424 B
// =====================================================================
#define FQS 68
#define FKS 68
#define FVS 132
#define KOFF 34816                 // 128*68*4
#define KSZ  17408                 // 64*68*4
#define VOFF (KOFF + 2*KSZ)        // 69632
#define VSZ  16896                 // 32*132*4
#define FLASH_SMEM (VOFF + 2*VSZ)  // 103424

__global__ void __launch_bounds__(256) flash_fp16()
{
    extern __shared__ char smem[];
    uint32_t* Qs  = (uint32_t*)smem;
    const uint32_t sb = smem_u32(smem);

    const int tid = threadIdx.x;
    const int qt  = gridDim.x - 1 - blockIdx.x;   // big tiles first
    const int h   = blockIdx.y;
    const int b   = blockIdx.z;
    const int kh  = h >> 2;
    const int t0  = qt * 128;
    const int wm  = (tid >> 5) * 16;
    const int lane = tid & 31;
    const int g = lane >> 2, tg = lane & 3;

    const uint32_t* kg = g_Ktp + (long)(b*KVH_ + kh) * 64 * T_;      // [dpair][s]
    const uint32_t* vg = g_Vp  + (long)(b*KVH_ + kh) * (T_/2) * HD_; // [spair][d]
    const float scale = 0.08838834764831845f;

    // ---- Q tile: LDG fp32 -> scale -> fp16x2 pack -> smem ----
    {
        const float* qgp = g_Q + (long)(b*T_ + t0) * (H_*HD_) + h*HD_;
#pragma unroll
        for (int it = 0; it < 16; it++) {
            int idx = tid + it*256;
            int r = idx >> 5, d4 = (idx & 31) * 4;
            float4 v = *(const float4*)(qgp + (long)r*(H_*HD_) + d4);
            uint32_t p0 = pack_h2(v.x * scale, v.y * scale);
            uint32_t p1 = pack_h2(v.z * scale, v.w * scale);
            *(uint2*)&Qs[r*FQS + d4/2] = make_uint2(p0, p1);
        }
    }

    const int nkt = 2*qt + 2;

    // ---- prologue: tile 0 -> buffer 0 ----
    {
        // K tile: 64 dpair rows x 64 s u32 (4 cp16 per thread)
#pragma unroll
        for (int i = 0; i < 4; i++) {
            int idx = tid + i*256;
            int d = idx >> 4, c4 = (idx & 15) * 4;
            CPA16(sb + KOFF + (d*FKS + c4)*4, (const void*)(kg + (long)d*T_ + c4));
        }
        // V tile: 32 spair rows x 128 d (4 cp16 per thread)
#pragma unroll
        for (int i = 0; i < 4; i++) {
            int idx = tid + i*256;
            int c = idx >> 5, d4 = (idx & 31) * 4;
            CPA16(sb + VOFF + (c*FVS + d4)*4, (const void*)(vg + (long)c*HD_ + d4));
        }
        CP_COMMIT();
    }

    float o[16][4];
#pragma unroll
    for (int nt = 0; nt < 16; nt++)
#pragma unroll
        for (int i = 0; i < 4; i++) o[nt][i] = 0.f;
    float m0 = -1e30f, m1 = -1e30f, l0 = 0.f, l1 = 0.f;

    for (int kt = 0; kt < nkt; kt++) {
        const int cur = kt & 1;
        if (kt + 1 < nkt) {
            const int s0n = (kt + 1) * 64;
            const int sel = cur ^ 1;
#pragma unroll
            for (int i = 0; i < 4; i++) {
                int idx = tid + i*256;
                int d = idx >> 4, c4 = (idx & 15) * 4;
                CPA16(sb + KOFF + sel*KSZ + (d*FKS + c4)*4,
                      (const void*)(kg + (long)d*T_ + s0n + c4));
            }
#pragma unroll
            for (int i = 0; i < 4; i++) {
                int idx = tid + i*256;
                int c = idx >> 5, d4 = (idx & 31) * 4;
                CPA16(sb + VOFF + sel*VSZ + (c*FVS + d4)*4,
                      (const void*)(vg + (long)(s0n/2 + c)*HD_ + d4));
            }
            CP_COMMIT();
            CP_WAIT1();
        } else {
            CP_WAIT0();
        }
        __syncthreads();

        const uint32_t* Kc = (const uint32_t*)(smem + KOFF + cur*KSZ);
        const uint32_t* Vc = (const uint32_t*)(smem + VOFF + cur*VSZ);

        // ---- S = Q @ K^T (fp16 k16 mma, 8 slices over d=128) ----
        float sf[8][4];
#pragma unroll
        for (int nt = 0; nt < 8; nt++)
#pragma unroll
            for (int i = 0; i < 4; i++) sf[nt][i] = 0.f;

#pragma unroll
        for (int kd = 0; kd < 8; kd++) {
            uint32_t a[4];
            a[0] = Qs[(wm+g)*FQS   + kd*8 + tg];
            a[1] = Qs[(wm+g+8)*FQS + kd*8 + tg];
            a[2] = Qs[(wm+g)*FQS   + kd*8 + tg + 4];
            a[3] = Qs[(wm+g+8)*FQS + kd*8 + tg + 4];
#pragma unroll
            for (int nt = 0; nt < 8; nt++) {
                uint32_t bb[2];
                bb[0] = Kc[(kd*8+tg)*FKS   + nt*8 + g];
                bb[1] = Kc[(kd*8+tg+4)*FKS + nt*8 + g];
                mma_fp16(sf[nt], a, bb);
            }
        }

        // ---- causal mask (diagonal tiles only) ----
        if (kt >= nkt - 2) {
            const int s0c = kt * 64;
            const int r0 = t0 + wm + g, r1 = r0 + 8;
#pragma unroll
            for (int nt = 0; nt < 8; nt++) {
                int c0 = s0c + nt*8 + 2*tg;
                if (c0     > r0) sf[nt][0] = -1e30f;
                if (c0 + 1 > r0) sf[nt][1] = -1e30f;
                if (c0     > r1) sf[nt][2] = -1e30f;
                if (c0 + 1 > r1) sf[nt][3] = -1e30f;
            }
        }

        // ---- online softmax (registers only) ----
        float mt0 = -1e30f, mt1 = -1e30f;
#pragma unroll
        for (int nt = 0; nt < 8; nt++) {
            mt0 = fmaxf(mt0, fmaxf(sf[nt][0], sf[nt][1]));
            mt1 = fmaxf(mt1, fmaxf(sf[nt][2], sf[nt][3]));
        }
        mt0 = fmaxf(mt0, __shfl_xor_sync(0xffffffffu, mt0, 1));
        mt0 = fmaxf(mt0, __shfl_xor_sync(0xffffffffu, mt0, 2));
        mt1 = fmaxf(mt1, __shfl_xor_sync(0xffffffffu, mt1, 1));
        mt1 = fmaxf(mt1, __shfl_xor_sync(0xffffffffu, mt1, 2));

        float mn0 = fmaxf(m0, mt0), mn1 = fmaxf(m1, mt1);
        float al0 = __expf(m0 - mn0), al1 = __expf(m1 - mn1);
        m0 = mn0; m1 = mn1;

        float rs0 = 0.f, rs1 = 0.f;
        uint32_t pf01[8], pf23[8];
#pragma unroll
        for (int nt = 0; nt < 8; nt++) {
            float p0 = __expf(sf[nt][0] - mn0);
            float p1 = __expf(sf[nt][1] - mn0);
            float p2 = __expf(sf[nt][2] - mn1);
            float p3 = __expf(sf[nt][3] - mn1);
            rs0 += p0 + p1; rs1 += p2 + p3;
            pf01[nt] = pack_h2(p0, p1);
            pf23[nt] = pack_h2(p2, p3);
        }
        rs0 += __shfl_xor_sync(0xffffffffu, rs0, 1);
        rs0 += __shfl_xor_sync(0xffffffffu, rs0, 2);
        rs1 += __shfl_xor_sync(0xffffffffu, rs1, 1);
        rs1 += __shfl_xor_sync(0xffffffffu, rs1, 2);
        l0 = l0 * al0 + rs0;
        l1 = l1 * al1 + rs1;

#pragma unroll
        for (int nt = 0; nt < 16; nt++) {
            o[nt][0] *= al0; o[nt][1] *= al0;
            o[nt][2] *= al1; o[nt][3] *= al1;
        }

        // ---- O += P @ V (P c-frags ARE the k16 A-frags; no shuffles) ----
#pragma unroll
        for (int ks = 0; ks < 4; ks++) {
            uint32_t a[4];
            a[0] = pf01[2*ks];     // row g,   k = 2tg,2tg+1  (s = 16ks+2tg)
            a[1] = pf23[2*ks];     // row g+8
            a[2] = pf01[2*ks + 1]; // row g,   k = 2tg+8,2tg+9
            a[3] = pf23[2*ks + 1]; // row g+8
#pragma unroll
            for (int nt = 0; nt < 16; nt++) {
                uint32_t bb[2];
                bb[0] = Vc[(ks*8+tg)*FVS   + nt*8 + g];
                bb[1] = Vc[(ks*8+tg+4)*FVS + nt*8 + g];
                mma_fp16(o[nt], a, bb);
            }
        }
        __syncthreads();
    }

    // ---- epilogue: normalize + fp16 pack into g_Op ----
    const float inv0 = 1.0f / l0, inv1 = 1.0f / l1;
    const long row0 = (long)(b*T_ + t0 + wm + g);
    const long row1 = row0 + 8;
    const int colbase = h * 64;   // 64 packed cols per head
#pragma unroll
    for (int nt = 0; nt < 16; nt++) {
        int p = colbase + nt*4 + tg;
        g_Op[row0*KU + p] = pack_h2(o[nt][0]*inv0, o[nt][1]*inv0);
        g_Op[row1*KU + p] = pack_h2(o[nt][2]*inv1, o[nt][3]*inv1);
    }
}

// =====================================================================
// host launcher
// =====================================================================
extern "C" void kernel_launch(void* const* d_in, const int* in_sizes, int n_in,
                              void* d_out, int out_size)
{
    const float* x  = (const float*)d_in[0];
    const float* wq = (const float*)d_in[1];
    const float* bq = (const float*)d_in[2];
    const float* wk = (const float*)d_in[3];
    const float* bk = (const float*)d_in[4];
    const float* wv = (const float*)d_in[5];
    const float* bv = (const float*)d_in[6];
    const float* wo = (const float*)d_in[7];
    float* out = (float*)d_out;

    float *qp, *kp, *vp;
    uint32_t *xp, *wqp, *wkp, *wvp, *wop;
    cudaGetSymbolAddress((void**)&qp, g_Q);
    cudaGetSymbolAddress((void**)&kp, g_K);
    cudaGetSymbolAddress((void**)&vp, g_V);
    cudaGetSymbolAddress((void**)&xp,  g_Xp);
    cudaGetSymbolAddress((void**)&wqp, g_Wqp);
    cudaGetSymbolAddress((void**)&wkp, g_Wkp);
    cudaGetSymbolAddress((void**)&wvp, g_Wvp);
    cudaGetSymbolAddress((void**)&wop, g_Wop);

    cudaFuncSetAttribute(flash_fp16,
                         cudaFuncAttributeMaxDynamicSharedMemorySize, FLASH_SMEM);
    cudaFuncSetAttribute(qkv_mma,
                         cudaFuncAttributeMaxDynamicSharedMemorySize, GEMM_SMEM);
    cudaFuncSetAttribute(out_mma,
                         cudaFuncAttributeMaxDynamicSharedMemorySize, GEMM_SMEM);

    dim3 blk(256);

    // fp16 packing of GEMM operands
    pack_row <<<(MROWS*KU)/256, blk>>>(x, xp, MROWS*KU);
    pack_kmaj<<<(KU*(H_*HD_))/256,   blk>>>(wq, wqp, H_*HD_,   KU*(H_*HD_));
    pack_kmaj<<<(KU*(KVH_*HD_))/256, blk>>>(wk, wkp, KVH_*HD_, KU*(KVH_*HD_));
    pack_kmaj<<<(KU*(KVH_*HD_))/256, blk>>>(wv, wvp, KVH_*HD_, KU*(KVH_*HD_));
    pack_kmaj<<<(KU*C_)/256,         blk>>>(wo, wop, C_,       KU*C_);

    // merged QKV projection (fp16 tensor cores)
    qkv_mma<<<dim3(24, MROWS/256), blk, GEMM_SMEM>>>(bq, qp, bk, kp, bv, vp);

    // RoPE
    rope_q_kernel<<<(B_*T_*H_*64)/256, blk>>>();
    ropeT_k_kernel<<<dim3(T_/32, 2, B_*KVH_), blk>>>();

    // pack K^T and V to fp16 pairs
    pack_kt<<<(B_*KVH_*64*T_)/256, blk>>>();
    pack_v <<<(B_*KVH_*(T_/2)*HD_)/256, blk>>>();

    // fp16 flash attention (writes packed O)
    flash_fp16<<<dim3(T_/128, H_, B_), blk, FLASH_SMEM>>>();

    // output projection (fp16)
    out_mma<<<dim3(C_/128, MROWS/256), blk, GEMM_SMEM>>>(out);
}

// round 15
// speedup vs baseline: 2.0593x; 1.0191x over previous
#include <cuda_runtime.h>
#include <math.h>
#include <stdint.h>

#define B_   2
#define T_   2048
#define C_   2048
#define H_   16
#define KVH_ 4
#define HD_  128
#define MROWS (B_*T_)   // 4096
#define KU   1024       // packed u32 columns (2048 fp16 pairs)

// ---------------- scratch (device globals; no allocations) ----------------
__device__ float g_Q[B_*T_*H_*HD_];          // fp32, raw (rope fused into flash)
__device__ float g_K[B_*T_*KVH_*HD_];        // fp32
__device__ float g_V[B_*T_*KVH_*HD_];        // fp32
// fp16-packed operands (u32 = hi<<16 | lo, lo = even index)
__device__ uint32_t g_Xp[MROWS*KU];
__device__ uint32_t g_Op[MROWS*KU];          // attention out, packed by flash
__device__ uint32_t g_Wqp[KU*(H_*HD_)];
__device__ uint32_t g_Wkp[KU*(KVH_*HD_)];
__device__ uint32_t g_Wvp[KU*(KVH_*HD_)];
__device__ uint32_t g_Wop[KU*C_];
__device__ uint32_t g_Ktp[B_*KVH_*64*T_];    // roped K^T packed along d: [bkh][dpair][s]
__device__ uint32_t g_Vp[B_*KVH_*(T_/2)*HD_];// V packed along s: [bkh][spair][d]

// ==================== helpers ====================
__device__ __forceinline__ uint32_t smem_u32(const void* p) {
    uint32_t a;
    asm("{ .reg .u64 t; cvta.to.shared.u64 t, %1; cvt.u32.u64 %0, t; }"
        : "=r"(a) : "l"(p));
    return a;
}

// pack two floats into fp16x2 (x0 -> low half, x1 -> high half)
__device__ __forceinline__ uint32_t pack_h2(float x0, float x1) {
    uint32_t r;
    asm("cvt.rn.f16x2.f32 %0, %1, %2;" : "=r"(r) : "f"(x1), "f"(x0));
    return r;
}

__device__ __forceinline__ void mma_fp16(float* c, const uint32_t* a, const uint32_t* b) {
    asm volatile(
        "mma.sync.aligned.m16n8k16.row.col.f32.f16.f16.f32 "
        "{%0,%1,%2,%3}, {%4,%5,%6,%7}, {%8,%9}, {%0,%1,%2,%3};"
        : "+f"(c[0]), "+f"(c[1]), "+f"(c[2]), "+f"(c[3])
        : "r"(a[0]), "r"(a[1]), "r"(a[2]), "r"(a[3]), "r"(b[0]), "r"(b[1]));
}

#define CPA16(dst, src) \
    asm volatile("cp.async.cg.shared.global [%0], [%1], 16;" \
                 :: "r"(dst), "l"(src) : "memory")
#define CP_COMMIT() asm volatile("cp.async.commit_group;" ::: "memory")
#define CP_WAIT1()  asm volatile("cp.async.wait_group 1;" ::: "memory")
#define CP_WAIT0()  asm volatile("cp.async.wait_group 0;" ::: "memory")

// =====================================================================
// pack_all: one kernel packs x + all four weights to fp16 pairs.
// Ranges (u32 outputs): x 4M | wq 2M | wk 0.5M | wv 0.5M | wo 2M = 9.4M
// =====================================================================
#define NXP ((long)MROWS*KU)
#define NQP ((long)KU*(H_*HD_))
#define NKP ((long)KU*(KVH_*HD_))
#define NOP ((long)KU*C_)
#define PACK_TOT (NXP + NQP + 2*NKP + NOP)

__global__ void __launch_bounds__(256) pack_all(
    const float* __restrict__ x,  const float* __restrict__ wq,
    const float* __restrict__ wk, const float* __restrict__ wv,
    const float* __restrict__ wo)
{
    long gi = (long)blockIdx.x * 256 + threadIdx.x;
    if (gi < NXP) {
        float2 v = *(const float2*)(x + gi * 2);
        g_Xp[gi] = pack_h2(v.x, v.y);
        return;
    }
    gi -= NXP;
    if (gi < NQP) {   // wq: N = 2048
        long kk = gi >> 11, c = gi & 2047;
        g_Wqp[gi] = pack_h2(wq[(2*kk)*2048 + c], wq[(2*kk+1)*2048 + c]);
        return;
    }
    gi -= NQP;
    if (gi < NKP) {   // wk: N = 512
        long kk = gi >> 9, c = gi & 511;
        g_Wkp[gi] = pack_h2(wk[(2*kk)*512 + c], wk[(2*kk+1)*512 + c]);
        return;
    }
    gi -= NKP;
    if (gi < NKP) {   // wv: N = 512
        long kk = gi >> 9, c = gi & 511;
        g_Wvp[gi] = pack_h2(wv[(2*kk)*512 + c], wv[(2*kk+1)*512 + c]);
        return;
    }
    gi -= NKP;        // wo: N = 2048
    {
        long kk = gi >> 11, c = gi & 2047;
        g_Wop[gi] = pack_h2(wo[(2*kk)*2048 + c], wo[(2*kk+1)*2048 + c]);
    }
}

// g_V [b*T+s][kh*128+d] -> g_Vp [bkh][sp][128] (pairs along s)
__global__ void __launch_bounds__(256) pack_v()
{
    int i = blockIdx.x * 256 + threadIdx.x;   // over 8*1024*128
    int d    = i & 127;
    int rest = i >> 7;
    int sp   = rest & 1023;
    int bkh  = rest >> 10;
    int b = bkh >> 2, kh = bkh & 3;
    long s0 = (long)(b*T_ + 2*sp) * (KVH_*HD_) + kh*HD_ + d;
    g_Vp[i] = pack_h2(g_V[s0], g_V[s0 + KVH_*HD_]);
}

// =====================================================================
// fp16 GEMM core: CTA 256x128, 8 warps (4m x 2n), warp 64x64.
// One m16n8k16 mma per k16 slice. 3-stage cp.async, one sync per stage.
// =====================================================================
#define ASTR 20
#define BSTR 132
#define A_ST (256*ASTR)
#define B_ST (16*BSTR)
#define GEMM_SMEM (3*(A_ST + B_ST)*4)

__device__ __forceinline__ void gemm_core(
    const uint32_t* __restrict__ Ap, const uint32_t* __restrict__ Wp,
    const float* __restrict__ bias, float* __restrict__ Cout,
    int N, int rowBlk, int colBlk)
{
    extern __shared__ uint32_t dsm[];
    uint32_t* As = dsm;                 // [3][A_ST]
    uint32_t* Bs = dsm + 3*A_ST;        // [3][B_ST]
    const uint32_t sbA = smem_u32(As);
    const uint32_t sbB = smem_u32(Bs);

    const int tid  = threadIdx.x;
    const int wid  = tid >> 5;
    const int lane = tid & 31;
    const int g    = lane >> 2;
    const int tg   = lane & 3;
    const int warp_m = (wid & 3) * 64;
    const int warp_n = (wid >> 2) * 64;

    float acc[4][8][4];
#pragma unroll
    for (int mt = 0; mt < 4; mt++)
#pragma unroll
        for (int nt = 0; nt < 8; nt++)
#pragma unroll
            for (int i = 0; i < 4; i++) acc[mt][nt][i] = 0.f;

    const int nit = KU / 16;   // 64 stages

    auto prefetch = [&](int t, int s) {
#pragma unroll
        for (int i = 0; i < 4; i++) {
            int idx = tid + i * 256;
            int r = idx >> 2, c = (idx & 3) * 4;
            CPA16(sbA + (uint32_t)(s*A_ST + r*ASTR + c) * 4u,
                  (const void*)(Ap + (long)(rowBlk + r) * KU + t*16 + c));
        }
#pragma unroll
        for (int i = 0; i < 2; i++) {
            int idx = tid + i * 256;
            int k = idx >> 5, n4 = (idx & 31) * 4;
            CPA16(sbB + (uint32_t)(s*B_ST + k*BSTR + n4) * 4u,
                  (const void*)(Wp + (long)(t*16 + k) * N + colBlk + n4));
        }
        CP_COMMIT();
    };

    prefetch(0, 0);
    prefetch(1, 1);

    for (int it = 0; it < nit; it++) {
        const int cur = it % 3;
        if (it == nit - 1) { CP_WAIT0(); } else { CP_WAIT1(); }
        __syncthreads();
        if (it + 2 < nit) prefetch(it + 2, (it + 2) % 3);

        const uint32_t* AS = As + cur * A_ST;
        const uint32_t* BS = Bs + cur * B_ST;

#pragma unroll
        for (int s = 0; s < 2; s++) {      // two k16 slices per stage
            uint32_t a[4][4];
#pragma unroll
            for (int mt = 0; mt < 4; mt++) {
                int row = warp_m + mt * 16 + g;
                int c0  = s * 8 + tg;
                a[mt][0] = AS[row * ASTR + c0];
                a[mt][1] = AS[(row + 8) * ASTR + c0];
                a[mt][2] = AS[row * ASTR + c0 + 4];
                a[mt][3] = AS[(row + 8) * ASTR + c0 + 4];
            }
#pragma unroll
            for (int nt = 0; nt < 8; nt++) {
                int col = warp_n + nt * 8 + g;
                uint32_t bb[2];
                bb[0] = BS[(s*8 + tg)     * BSTR + col];
                bb[1] = BS[(s*8 + tg + 4) * BSTR + col];
#pragma unroll
                for (int mt = 0; mt < 4; mt++)
                    mma_fp16(acc[mt][nt], a[mt], bb);
            }
        }
    }

#pragma unroll
    for (int mt = 0; mt < 4; mt++) {
        int row = rowBlk + warp_m + mt * 16 + g;
#pragma unroll
        for (int nt = 0; nt < 8; nt++) {
            int col = colBlk + warp_n + nt * 8 + 2 * tg;
            float b0 = 0.f, b1 = 0.f;
            if (bias) { b0 = bias[col]; b1 = bias[col + 1]; }
            float* c0 = Cout + (long)row * N + col;
            float* c1 = Cout + (long)(row + 8) * N + col;
            *(float2*)c0 = make_float2(acc[mt][nt][0] + b0, acc[mt][nt][1] + b1);
            *(float2*)c1 = make_float2(acc[mt][nt][2] + b0, acc[mt][nt][3] + b1);
        }
    }
}

// Merged QKV projection: grid (24, 16). bx<16: Q, <20: K, else V.
__global__ void __launch_bounds__(256, 1) qkv_mma(
    const float* __restrict__ bq, float* __restrict__ qp,
    const float* __restrict__ bk, float* __restrict__ kp,
    const float* __restrict__ bv, float* __restrict__ vp)
{
    const int bx = blockIdx.x;
    const int rowBlk = blockIdx.y * 256;
    if (bx < 16)
        gemm_core(g_Xp, g_Wqp, bq, qp, H_*HD_,   rowBlk, bx * 128);
    else if (bx < 20)
        gemm_core(g_Xp, g_Wkp, bk, kp, KVH_*HD_, rowBlk, (bx - 16) * 128);
    else
        gemm_core(g_Xp, g_Wvp, bv, vp, KVH_*HD_, rowBlk, (bx - 20) * 128);
}

// Output projection: grid (16, 16)
__global__ void __launch_bounds__(256, 1) out_mma(float* __restrict__ out)
{
    gemm_core(g_Op, g_Wop, nullptr, out, C_, blockIdx.y * 256, blockIdx.x * 128);
}

// =====================================================================
// RoPE on K + transpose + fp16 d-pair pack, fused: writes g_Ktp directly.
// grid: (T/32, 2, B*KVH), block 256.
// Thread po=tid>>3 owns a d-pair output (po<16: low half, else high),
// sg=tid&7 covers 4 s-values.
// =====================================================================
__global__ void __launch_bounds__(256) ropeT_kp()
{
    __shared__ float sm1[32][33];
    __shared__ float sm2[32][33];
    const int tid = threadIdx.x;
    const int s0  = blockIdx.x * 32;
    const int d0  = blockIdx.y * 32;      // 0 or 32
    const int bkh = blockIdx.z;
    const int b   = bkh >> 2;
    const int kh  = bkh & 3;

    {
        int r  = tid >> 3;
        int c4 = (tid & 7) * 4;
        long gbase = (long)(b*T_ + s0 + r) * (KVH_*HD_) + kh * HD_;
        float4 v1 = *(const float4*)(g_K + gbase + d0 + c4);
        float4 v2 = *(const float4*)(g_K + gbase + d0 + 64 + c4);
        sm1[r][c4+0]=v1.x; sm1[r][c4+1]=v1.y; sm1[r][c4+2]=v1.z; sm1[r][c4+3]=v1.w;
        sm2[r][c4+0]=v2.x; sm2[r][c4+1]=v2.y; sm2[r][c4+2]=v2.z; sm2[r][c4+3]=v2.w;
    }
    __syncthreads();

    const int po = tid >> 3;          // 0..31
    const int sg = tid & 7;
    const int j  = po & 15;           // pair index within this d0 block
    const bool high = po >= 16;
    const float LN = 9.210340371976184f / 64.0f;
    float invf0 = expf(-(float)(d0 + 2*j)     * LN);
    float invf1 = expf(-(float)(d0 + 2*j + 1) * LN);
    int dpair = (high ? 32 : 0) + (d0 >> 1) + j;
    long obase = (long)(bkh * 64 + dpair) * T_;
#pragma unroll
    for (int i = 0; i < 4; i++) {
        int cc = sg * 4 + i;
        int t  = s0 + cc;
        float sn0, cs0, sn1, cs1;
        sincosf((float)t * invf0, &sn0, &cs0);
        sincosf((float)t * invf1, &sn1, &cs1);
        float a0 = sm1[cc][2*j],     b0v = sm2[cc][2*j];
        float a1 = sm1[cc][2*j + 1], b1v = sm2[cc][2*j + 1];
        float o0, o1;
        if (!high) { o0 = a0*cs0 - b0v*sn0; o1 = a1*cs1 - b1v*sn1; }
        else       { o0 = b0v*cs0 + a0*sn0; o1 = b1v*cs1 + a1*sn1; }
        g_Ktp[obase + t] = pack_h2(o0, o1);
    }
}

// =====================================================================
// fp16 tensor-core flash attention (causal, GQA), RoPE-on-Q fused in
// the prologue. BM=128, BN=64, 256 threads. m16n8k16 for S and PV.
// smem: Qs[128][68] | K[2][64][68] | V[2][32][132]  = 103424 B
// =====================================================================
#define FQS 68
#define FKS 68
#define FVS 132
#define KOFF 34816                 // 128*68*4
#define KSZ  17408                 // 64*68*4
#define VOFF (KOFF + 2*KSZ)        // 69632
#define VSZ  16896                 // 32*132*4
#define FLASH_SMEM (VOFF + 2*VSZ)  // 103424

__global__ void __launch_bounds__(256) flash_fp16()
{
    extern __shared__ char smem[];
    uint32_t* Qs  = (uint32_t*)smem;
    const uint32_t sb = smem_u32(smem);

    const int tid = threadIdx.x;
    const int qt  = gridDim.x - 1 - blockIdx.x;   // big tiles first
    const int h   = blockIdx.y;
    const int b   = blockIdx.z;
    const int kh  = h >> 2;
    const int t0  = qt * 128;
    const int wm  = (tid >> 5) * 16;
    const int lane = tid & 31;
    const int g = lane >> 2, tg = lane & 3;

    const uint32_t* kg = g_Ktp + (long)(b*KVH_ + kh) * 64 * T_;      // [dpair][s]
    const uint32_t* vg = g_Vp  + (long)(b*KVH_ + kh) * (T_/2) * HD_; // [spair][d]
    const float scale = 0.08838834764831845f;

    const int nkt = 2*qt + 2;

    // ---- prologue part 1: issue K/V cp.async for tile 0 ----
    {
#pragma unroll
        for (int i = 0; i < 4; i++) {
            int idx = tid + i*256;
            int d = idx >> 4, c4 = (idx & 15) * 4;
            CPA16(sb + KOFF + (d*FKS + c4)*4, (const void*)(kg + (long)d*T_ + c4));
        }
#pragma unroll
        for (int i = 0; i < 4; i++) {
            int idx = tid + i*256;
            int c = idx >> 5, d4 = (idx & 31) * 4;
            CPA16(sb + VOFF + (c*FVS + d4)*4, (const void*)(vg + (long)c*HD_ + d4));
        }
        CP_COMMIT();
    }

    // ---- prologue part 2: Q load + RoPE + scale + fp16 pack -> smem ----
    {
        const float* qgp = g_Q + (long)(b*T_ + t0) * (H_*HD_) + h*HD_;
        const float LN = 9.210340371976184f / 64.0f;
#pragma unroll
        for (int it = 0; it < 8; it++) {
            int idx = tid + it*256;        // 0..2047
            int r  = idx >> 4;             // row 0..127
            int gq = (idx & 15) * 4;       // d base 0..60
            int t  = t0 + r;
            float4 v1 = *(const float4*)(qgp + (long)r*(H_*HD_) + gq);
            float4 v2 = *(const float4*)(qgp + (long)r*(H_*HD_) + gq + 64);
            float x1[4] = {v1.x, v1.y, v1.z, v1.w};
            float x2[4] = {v2.x, v2.y, v2.z, v2.w};
            float lo[4], hi[4];
#pragma unroll
            for (int j = 0; j < 4; j++) {
                float invf = expf(-(float)(gq + j) * LN);
                float sn, cs;
                sincosf((float)t * invf, &sn, &cs);
                lo[j] = (x1[j]*cs - x2[j]*sn) * scale;
                hi[j] = (x2[j]*cs + x1[j]*sn) * scale;
            }
            *(uint2*)&Qs[r*FQS + gq/2] =
                make_uint2(pack_h2(lo[0], lo[1]), pack_h2(lo[2], lo[3]));
            *(uint2*)&Qs[r*FQS + 32 + gq/2] =
                make_uint2(pack_h2(hi[0], hi[1]), pack_h2(hi[2], hi[3]));
        }
    }

    float o[16][4];
#pragma unroll
    for (int nt = 0; nt < 16; nt++)
#pragma unroll
        for (int i = 0; i < 4; i++) o[nt][i] = 0.f;
    float m0 = -1e30f, m1 = -1e30f, l0 = 0.f, l1 = 0.f;

    for (int kt = 0; kt < nkt; kt++) {
        const int cur = kt & 1;
        if (kt + 1 < nkt) {
            const int s0n = (kt + 1) * 64;
            const int sel = cur ^ 1;
#pragma unroll
            for (int i = 0; i < 4; i++) {
                int idx = tid + i*256;
                int d = idx >> 4, c4 = (idx & 15) * 4;
                CPA16(sb + KOFF + sel*KSZ + (d*FKS + c4)*4,
                      (const void*)(kg + (long)d*T_ + s0n + c4));
            }
#pragma unroll
            for (int i = 0; i < 4; i++) {
                int idx = tid + i*256;
                int c = idx >> 5, d4 = (idx & 31) * 4;
                CPA16(sb + VOFF + sel*VSZ + (c*FVS + d4)*4,
                      (const void*)(vg + (long)(s0n/2 + c)*HD_ + d4));
            }
            CP_COMMIT();
            CP_WAIT1();
        } else {
            CP_WAIT0();
        }
        __syncthreads();

        const uint32_t* Kc = (const uint32_t*)(smem + KOFF + cur*KSZ);
        const uint32_t* Vc = (const uint32_t*)(smem + VOFF + cur*VSZ);

        // ---- S = Q @ K^T (fp16 k16 mma, 8 slices over d=128) ----
        float sf[8][4];
#pragma unroll
        for (int nt = 0; nt < 8; nt++)
#pragma unroll
            for (int i = 0; i < 4; i++) sf[nt][i] = 0.f;

#pragma unroll
        for (int kd = 0; kd < 8; kd++) {
            uint32_t a[4];
            a[0] = Qs[(wm+g)*FQS   + kd*8 + tg];
            a[1] = Qs[(wm+g+8)*FQS + kd*8 + tg];
            a[2] = Qs[(wm+g)*FQS   + kd*8 + tg + 4];
            a[3] = Qs[(wm+g+8)*FQS + kd*8 + tg + 4];
#pragma unroll
            for (int nt = 0; nt < 8; nt++) {
                uint32_t bb[2];
                bb[0] = Kc[(kd*8+tg)*FKS   + nt*8 + g];
                bb[1] = Kc[(kd*8+tg+4)*FKS + nt*8 + g];
                mma_fp16(sf[nt], a, bb);
            }
        }

        // ---- causal mask (diagonal tiles only) ----
        if (kt >= nkt - 2) {
            const int s0c = kt * 64;
            const int r0 = t0 + wm + g, r1 = r0 + 8;
#pragma unroll
            for (int nt = 0; nt < 8; nt++) {
                int c0 = s0c + nt*8 + 2*tg;
                if (c0     > r0) sf[nt][0] = -1e30f;
                if (c0 + 1 > r0) sf[nt][1] = -1e30f;
                if (c0     > r1) sf[nt][2] = -1e30f;
                if (c0 + 1 > r1) sf[nt][3] = -1e30f;
            }
        }

        // ---- online softmax (registers only) ----
        float mt0 = -1e30f, mt1 = -1e30f;
#pragma unroll
        for (int nt = 0; nt < 8; nt++) {
            mt0 = fmaxf(mt0, fmaxf(sf[nt][0], sf[nt][1]));
            mt1 = fmaxf(mt1, fmaxf(sf[nt][2], sf[nt][3]));
        }
        mt0 = fmaxf(mt0, __shfl_xor_sync(0xffffffffu, mt0, 1));
        mt0 = fmaxf(mt0, __shfl_xor_sync(0xffffffffu, mt0, 2));
        mt1 = fmaxf(mt1, __shfl_xor_sync(0xffffffffu, mt1, 1));
        mt1 = fmaxf(mt1, __shfl_xor_sync(0xffffffffu, mt1, 2));

        float mn0 = fmaxf(m0, mt0), mn1 = fmaxf(m1, mt1);
        float al0 = __expf(m0 - mn0), al1 = __expf(m1 - mn1);
        m0 = mn0; m1 = mn1;

        float rs0 = 0.f, rs1 = 0.f;
        uint32_t pf01[8], pf23[8];
#pragma unroll
        for (int nt = 0; nt < 8; nt++) {
            float p0 = __expf(sf[nt][0] - mn0);
            float p1 = __expf(sf[nt][1] - mn0);
            float p2 = __expf(sf[nt][2] - mn1);
            float p3 = __expf(sf[nt][3] - mn1);
            rs0 += p0 + p1; rs1 += p2 + p3;
            pf01[nt] = pack_h2(p0, p1);
            pf23[nt] = pack_h2(p2, p3);
        }
        rs0 += __shfl_xor_sync(0xffffffffu, rs0, 1);
        rs0 += __shfl_xor_sync(0xffffffffu, rs0, 2);
        rs1 += __shfl_xor_sync(0xffffffffu, rs1, 1);
        rs1 += __shfl_xor_sync(0xffffffffu, rs1, 2);
        l0 = l0 * al0 + rs0;
        l1 = l1 * al1 + rs1;

#pragma unroll
        for (int nt = 0; nt < 16; nt++) {
            o[nt][0] *= al0; o[nt][1] *= al0;
            o[nt][2] *= al1; o[nt][3] *= al1;
        }

        // ---- O += P @ V (P c-frags ARE the k16 A-frags; no shuffles) ----
#pragma unroll
        for (int ks = 0; ks < 4; ks++) {
            uint32_t a[4];
            a[0] = pf01[2*ks];
            a[1] = pf23[2*ks];
            a[2] = pf01[2*ks + 1];
            a[3] = pf23[2*ks + 1];
#pragma unroll
            for (int nt = 0; nt < 16; nt++) {
                uint32_t bb[2];
                bb[0] = Vc[(ks*8+tg)*FVS   + nt*8 + g];
                bb[1] = Vc[(ks*8+tg+4)*FVS + nt*8 + g];
                mma_fp16(o[nt], a, bb);
            }
        }
        __syncthreads();
    }

    // ---- epilogue: normalize + fp16 pack into g_Op ----
    const float inv0 = 1.0f / l0, inv1 = 1.0f / l1;
    const long row0 = (long)(b*T_ + t0 + wm + g);
    const long row1 = row0 + 8;
    const int colbase = h * 64;
#pragma unroll
    for (int nt = 0; nt < 16; nt++) {
        int p = colbase + nt*4 + tg;
        g_Op[row0*KU + p] = pack_h2(o[nt][0]*inv0, o[nt][1]*inv0);
        g_Op[row1*KU + p] = pack_h2(o[nt][2]*inv1, o[nt][3]*inv1);
    }
}

// =====================================================================
// host launcher
// =====================================================================
extern "C" void kernel_launch(void* const* d_in, const int* in_sizes, int n_in,
                              void* d_out, int out_size)
{
    const float* x  = (const float*)d_in[0];
    const float* wq = (const float*)d_in[1];
    const float* bq = (const float*)d_in[2];
    const float* wk = (const float*)d_in[3];
    const float* bk = (const float*)d_in[4];
    const float* wv = (const float*)d_in[5];
    const float* bv = (const float*)d_in[6];
    const float* wo = (const float*)d_in[7];
    float* out = (float*)d_out;

    float *qp, *kp, *vp;
    cudaGetSymbolAddress((void**)&qp, g_Q);
    cudaGetSymbolAddress((void**)&kp, g_K);
    cudaGetSymbolAddress((void**)&vp, g_V);

    cudaFuncSetAttribute(flash_fp16,
                         cudaFuncAttributeMaxDynamicSharedMemorySize, FLASH_SMEM);
    cudaFuncSetAttribute(qkv_mma,
                         cudaFuncAttributeMaxDynamicSharedMemorySize, GEMM_SMEM);
    cudaFuncSetAttribute(out_mma,
                         cudaFuncAttributeMaxDynamicSharedMemorySize, GEMM_SMEM);

    dim3 blk(256);

    // one-shot packing of x + all weights
    pack_all<<<(int)(PACK_TOT / 256), blk>>>(x, wq, wk, wv, wo);

    // merged QKV projection (fp16 tensor cores)
    qkv_mma<<<dim3(24, MROWS/256), blk, GEMM_SMEM>>>(bq, qp, bk, kp, bv, vp);

    // K: RoPE + transpose + fp16 pack (fused); V: fp16 s-pair pack
    ropeT_kp<<<dim3(T_/32, 2, B_*KVH_), blk>>>();
    pack_v  <<<(B_*KVH_*(T_/2)*HD_)/256, blk>>>();

    // flash attention (RoPE-on-Q fused; writes packed O)
    flash_fp16<<<dim3(T_/128, H_, B_), blk, FLASH_SMEM>>>();

    // output projection (fp16)
    out_mma<<<dim3(C_/128, MROWS/256), blk, GEMM_SMEM>>>(out);
}